// round 3
// baseline (speedup 1.0000x reference)
#include <cuda_runtime.h>
#include <cstdint>

#define NF  16384   // n_features
#define ND  768     // d_model
#define NBS 1024    // B*S
#define NM  262144  // n_connections

// Scratch (device globals — no cudaMalloc allowed)
__device__ __align__(16) float g_decT[(size_t)NF * ND];   // up_decoder transposed [F, D]
__device__ __align__(16) float g_upT [(size_t)NF * NBS];  // up_facts transposed  [F, BS]
__device__ __align__(16) float g_outT[(size_t)NF * NBS];  // output transposed    [F, BS]
__device__ __align__(16) float g_vals[NM];
__device__ int g_seg[NF + 1];

// ---------------------------------------------------------------------------
// Generic 32x32 tiled transpose: in[rows][cols] -> out[cols][rows].
// All dims here are multiples of 32, no bounds checks needed.
// Launch: grid(cols/32, rows/32), block(32, 8).
// ---------------------------------------------------------------------------
__global__ void transpose32(const float* __restrict__ in, float* __restrict__ out,
                            int rows, int cols) {
    __shared__ float tile[32][33];
    int c0 = blockIdx.x * 32;
    int r0 = blockIdx.y * 32;
    int x = threadIdx.x, y = threadIdx.y;
#pragma unroll
    for (int k = 0; k < 32; k += 8) {
        tile[y + k][x] = in[(size_t)(r0 + y + k) * cols + (c0 + x)];
    }
    __syncthreads();
#pragma unroll
    for (int k = 0; k < 32; k += 8) {
        out[(size_t)(c0 + y + k) * rows + (r0 + x)] = tile[x][y + k];
    }
}

// ---------------------------------------------------------------------------
// Segment boundaries: g_seg[f] = first m with i_indices[m] >= f (i sorted).
// ---------------------------------------------------------------------------
__global__ void segstart_kernel(const int* __restrict__ iidx) {
    int f = blockIdx.x * blockDim.x + threadIdx.x;
    if (f > NF) return;
    int lo = 0, hi = NM;
    while (lo < hi) {
        int mid = (lo + hi) >> 1;
        if (iidx[mid] < f) lo = mid + 1; else hi = mid;
    }
    g_seg[f] = lo;
}

// ---------------------------------------------------------------------------
// values[m] = dot(down_encoder[i_m, :], decT[j_m, :])  over D=768.
// One warp per connection; float4 loads, 6 iters per lane, shfl reduce.
// Sorted i -> consecutive warps reuse the same encoder row via L1.
// ---------------------------------------------------------------------------
__global__ void values_kernel(const float* __restrict__ enc,
                              const int* __restrict__ iidx,
                              const int* __restrict__ jidx) {
    int gw   = (blockIdx.x * blockDim.x + threadIdx.x) >> 5;
    int lane = threadIdx.x & 31;
    if (gw >= NM) return;
    int i = iidx[gw];
    int j = jidx[gw];
    const float4* a = (const float4*)(enc    + (size_t)i * ND);
    const float4* b = (const float4*)(g_decT + (size_t)j * ND);
    float s = 0.f;
#pragma unroll
    for (int k = 0; k < 6; k++) {                 // 6 * 32 * 4 = 768
        float4 x = a[lane + 32 * k];
        float4 y = b[lane + 32 * k];
        s += x.x * y.x + x.y * y.y + x.z * y.z + x.w * y.w;
    }
#pragma unroll
    for (int off = 16; off; off >>= 1)
        s += __shfl_xor_sync(0xFFFFFFFFu, s, off);
    if (lane == 0) g_vals[gw] = s;
}

// ---------------------------------------------------------------------------
// Segment reduce: outT[f, :] = sum_{m in seg(f)} vals[m] * upT[j_m, :].
// One CTA per f; 256 threads each own one float4 of the 1024-wide BS axis.
// Sorted i -> no atomics; empty segments write zeros (d_out is poisoned).
// ---------------------------------------------------------------------------
__global__ void scatter_kernel(const int* __restrict__ jidx) {
    int f = blockIdx.x;
    int t = threadIdx.x;  // 0..255
    int s0 = g_seg[f], s1 = g_seg[f + 1];
    const float4* up = (const float4*)g_upT;   // [F][BS/4]
    float4 acc = make_float4(0.f, 0.f, 0.f, 0.f);
    for (int m = s0; m < s1; m++) {
        float v = g_vals[m];
        int   j = jidx[m];
        float4 u = up[(size_t)j * (NBS / 4) + t];
        acc.x += v * u.x;
        acc.y += v * u.y;
        acc.z += v * u.z;
        acc.w += v * u.w;
    }
    ((float4*)g_outT)[(size_t)f * (NBS / 4) + t] = acc;
}

// ---------------------------------------------------------------------------
extern "C" void kernel_launch(void* const* d_in, const int* in_sizes, int n_in,
                              void* d_out, int out_size) {
    const float* up_facts = (const float*)d_in[0];  // [B,S,F] = [BS, F]
    const float* enc      = (const float*)d_in[1];  // [F, D]  down_encoder
    const float* dec      = (const float*)d_in[2];  // [D, F]  up_decoder
    const int*   iidx     = (const int*)d_in[3];    // [M] int32 (JAX x64 off), sorted
    const int*   jidx     = (const int*)d_in[4];    // [M] int32
    float*       out      = (float*)d_out;          // [BS, F]

    float* decT = nullptr; float* upT = nullptr; float* outT = nullptr;
    cudaGetSymbolAddress((void**)&decT, g_decT);
    cudaGetSymbolAddress((void**)&upT,  g_upT);
    cudaGetSymbolAddress((void**)&outT, g_outT);

    dim3 tb(32, 8);

    // 1. Dec [D,F] -> decT [F,D]
    transpose32<<<dim3(NF / 32, ND / 32), tb>>>(dec, decT, ND, NF);
    // 2. up_facts [BS,F] -> upT [F,BS]
    transpose32<<<dim3(NF / 32, NBS / 32), tb>>>(up_facts, upT, NBS, NF);
    // 3. segment starts
    segstart_kernel<<<(NF + 1 + 255) / 256, 256>>>(iidx);
    // 4. per-connection dot products (M warps)
    values_kernel<<<(NM * 32) / 256, 256>>>(enc, iidx, jidx);
    // 5. segment reduction into outT
    scatter_kernel<<<NF, 256>>>(jidx);
    // 6. outT [F,BS] -> out [BS,F]
    transpose32<<<dim3(NBS / 32, NF / 32), tb>>>(outT, out, NF, NBS);
}

// round 4
// speedup vs baseline: 1.3639x; 1.3639x over previous
#include <cuda_runtime.h>
#include <cuda_fp16.h>
#include <cstdint>

#define NF  16384   // n_features
#define ND  768     // d_model
#define NBS 1024    // B*S
#define NM  262144  // n_connections

// Scratch (device globals — no cudaMalloc allowed)
__device__ __align__(16) float  g_decT[(size_t)NF * ND];   // up_decoder transposed [F, D] fp32
__device__ __align__(16) __half g_upH [(size_t)NF * NBS];  // up_facts transposed  [F, BS] fp16
__device__ __align__(16) float  g_outT[(size_t)NF * NBS];  // output transposed    [F, BS] fp32
__device__ __align__(16) float  g_vals[NM];
__device__ int g_seg[NF + 1];

// ---------------------------------------------------------------------------
// 32x32 tiled transpose fp32 -> fp32
// ---------------------------------------------------------------------------
__global__ void transpose32(const float* __restrict__ in, float* __restrict__ out,
                            int rows, int cols) {
    __shared__ float tile[32][33];
    int c0 = blockIdx.x * 32;
    int r0 = blockIdx.y * 32;
    int x = threadIdx.x, y = threadIdx.y;
#pragma unroll
    for (int k = 0; k < 32; k += 8)
        tile[y + k][x] = in[(size_t)(r0 + y + k) * cols + (c0 + x)];
    __syncthreads();
#pragma unroll
    for (int k = 0; k < 32; k += 8)
        out[(size_t)(c0 + y + k) * rows + (r0 + x)] = tile[x][y + k];
}

// ---------------------------------------------------------------------------
// 32x32 tiled transpose fp32 -> fp16
// ---------------------------------------------------------------------------
__global__ void transpose32_h(const float* __restrict__ in, __half* __restrict__ out,
                              int rows, int cols) {
    __shared__ float tile[32][33];
    int c0 = blockIdx.x * 32;
    int r0 = blockIdx.y * 32;
    int x = threadIdx.x, y = threadIdx.y;
#pragma unroll
    for (int k = 0; k < 32; k += 8)
        tile[y + k][x] = in[(size_t)(r0 + y + k) * cols + (c0 + x)];
    __syncthreads();
#pragma unroll
    for (int k = 0; k < 32; k += 8)
        out[(size_t)(c0 + y + k) * rows + (r0 + x)] = __float2half_rn(tile[x][y + k]);
}

// ---------------------------------------------------------------------------
// Segment boundaries: g_seg[f] = first m with i_indices[m] >= f (i sorted).
// ---------------------------------------------------------------------------
__global__ void segstart_kernel(const int* __restrict__ iidx) {
    int f = blockIdx.x * blockDim.x + threadIdx.x;
    if (f > NF) return;
    int lo = 0, hi = NM;
    while (lo < hi) {
        int mid = (lo + hi) >> 1;
        if (iidx[mid] < f) lo = mid + 1; else hi = mid;
    }
    g_seg[f] = lo;
}

// ---------------------------------------------------------------------------
// values v2: each warp handles 4 consecutive connections; the Enc row is
// cached in registers and reused while i stays the same (i is sorted, avg
// run length 16). Cuts L1 traffic from 6KB to ~3.2KB per connection.
// ---------------------------------------------------------------------------
#define VG 4
__global__ void values_kernel(const float* __restrict__ enc,
                              const int* __restrict__ iidx,
                              const int* __restrict__ jidx) {
    int warp = (blockIdx.x * blockDim.x + threadIdx.x) >> 5;
    int lane = threadIdx.x & 31;
    int m0 = warp * VG;
    if (m0 >= NM) return;

    float4 a0, a1, a2, a3, a4, a5;
    int prev_i = -1;

#pragma unroll
    for (int g = 0; g < VG; g++) {
        int m = m0 + g;
        int i = iidx[m];
        int j = jidx[m];
        if (i != prev_i) {
            const float4* ap = (const float4*)(enc + (size_t)i * ND);
            a0 = ap[lane];       a1 = ap[lane + 32];  a2 = ap[lane + 64];
            a3 = ap[lane + 96];  a4 = ap[lane + 128]; a5 = ap[lane + 160];
            prev_i = i;
        }
        const float4* bp = (const float4*)(g_decT + (size_t)j * ND);
        float4 b0 = bp[lane];       float4 b1 = bp[lane + 32];
        float4 b2 = bp[lane + 64];  float4 b3 = bp[lane + 96];
        float4 b4 = bp[lane + 128]; float4 b5 = bp[lane + 160];

        float s = a0.x * b0.x + a0.y * b0.y + a0.z * b0.z + a0.w * b0.w;
        s += a1.x * b1.x + a1.y * b1.y + a1.z * b1.z + a1.w * b1.w;
        s += a2.x * b2.x + a2.y * b2.y + a2.z * b2.z + a2.w * b2.w;
        s += a3.x * b3.x + a3.y * b3.y + a3.z * b3.z + a3.w * b3.w;
        s += a4.x * b4.x + a4.y * b4.y + a4.z * b4.z + a4.w * b4.w;
        s += a5.x * b5.x + a5.y * b5.y + a5.z * b5.z + a5.w * b5.w;

#pragma unroll
        for (int off = 16; off; off >>= 1)
            s += __shfl_xor_sync(0xFFFFFFFFu, s, off);
        if (lane == 0) g_vals[m] = s;
    }
}

// ---------------------------------------------------------------------------
// Scatter v2: outT[f, :] = sum_{m in seg(f)} vals[m] * upH[j_m, :]  (fp16 rows,
// fp32 accumulate). (j, v) pairs staged in smem per 128-chunk. One CTA per f,
// 256 threads each own 4 consecutive BS columns.
// ---------------------------------------------------------------------------
#define SCH 128
__global__ void scatter_kernel(const int* __restrict__ jidx) {
    int f = blockIdx.x;
    int t = threadIdx.x;  // 0..255
    int s0 = g_seg[f], s1 = g_seg[f + 1];

    __shared__ int   sj[SCH];
    __shared__ float sv[SCH];

    float4 acc = make_float4(0.f, 0.f, 0.f, 0.f);

    for (int base = s0; base < s1; base += SCH) {
        int len = min(SCH, s1 - base);
        __syncthreads();
        for (int k = t; k < len; k += 256) {
            sj[k] = jidx[base + k];
            sv[k] = g_vals[base + k];
        }
        __syncthreads();
        for (int k = 0; k < len; k++) {
            float v = sv[k];
            // row is 1024 halves = 512 half2; thread t takes half2 idx 2t, 2t+1
            const float2* row = (const float2*)(g_upH + (size_t)sj[k] * NBS) + t;
            float2 raw = *row;                       // 8 bytes = 4 halves
            __half2 h0 = *(__half2*)&raw.x;
            __half2 h1 = *(__half2*)&raw.y;
            float2 u0 = __half22float2(h0);
            float2 u1 = __half22float2(h1);
            acc.x += v * u0.x;
            acc.y += v * u0.y;
            acc.z += v * u1.x;
            acc.w += v * u1.y;
        }
    }
    ((float4*)g_outT)[(size_t)f * (NBS / 4) + t] = acc;
}

// ---------------------------------------------------------------------------
extern "C" void kernel_launch(void* const* d_in, const int* in_sizes, int n_in,
                              void* d_out, int out_size) {
    const float* up_facts = (const float*)d_in[0];  // [BS, F]
    const float* enc      = (const float*)d_in[1];  // [F, D]  down_encoder
    const float* dec      = (const float*)d_in[2];  // [D, F]  up_decoder
    const int*   iidx     = (const int*)d_in[3];    // [M] int32, sorted
    const int*   jidx     = (const int*)d_in[4];    // [M] int32
    float*       out      = (float*)d_out;          // [BS, F]

    float*  decT = nullptr; __half* upH = nullptr; float* outT = nullptr;
    cudaGetSymbolAddress((void**)&decT, g_decT);
    cudaGetSymbolAddress((void**)&upH,  g_upH);
    cudaGetSymbolAddress((void**)&outT, g_outT);

    dim3 tb(32, 8);

    // 1. Dec [D,F] -> decT [F,D] fp32
    transpose32<<<dim3(NF / 32, ND / 32), tb>>>(dec, decT, ND, NF);
    // 2. up_facts [BS,F] -> upH [F,BS] fp16
    transpose32_h<<<dim3(NF / 32, NBS / 32), tb>>>(up_facts, upH, NBS, NF);
    // 3. segment starts
    segstart_kernel<<<(NF + 1 + 255) / 256, 256>>>(iidx);
    // 4. per-connection dot products (NM/VG warps)
    values_kernel<<<(NM / VG) * 32 / 256, 256>>>(enc, iidx, jidx);
    // 5. segment reduction into outT
    scatter_kernel<<<NF, 256>>>(jidx);
    // 6. outT [F,BS] -> out [BS,F]
    transpose32<<<dim3(NBS / 32, NF / 32), tb>>>(outT, out, NF, NBS);
}